// round 1
// baseline (speedup 1.0000x reference)
#include <cuda_runtime.h>
#include <cuda_bf16.h>
#include <math.h>

#define B_   2
#define HRV_ 32
#define WRV_ 1024
#define NQPB 32768
#define MQ   65536
#define CRV_ 64
#define CB_  256
#define HB_  200
#define WB_  200
#define NV_  40000
#define DIM  128
#define NHEADS 8
#define NPTS 6

// ---------------- scratch (device globals; no allocation allowed) -------------
__device__ float g_Wv[CB_*DIM];
__device__ float g_bv[DIM];
__device__ float g_Wo[DIM*DIM];
__device__ float g_bo[DIM];
__device__ float g_Wsa[DIM*144];
__device__ float g_bsa[144];
__device__ float g_value[B_*NV_*DIM];     // [b, y*200+x, 128]
__device__ float g_Q0[MQ*DIM];
__device__ float g_h1[MQ*DIM];            // h1, then gelu(gn1(h1)) in place
__device__ float g_h2[MQ*64];
__device__ float g_q1[MQ*DIM];
__device__ float g_query[MQ*DIM];
__device__ float g_sigfeat[MQ*2];
__device__ float g_refpx[MQ*2];           // rx*200-0.5, ry*200-0.5
__device__ float g_sa[MQ*144];            // [offs(96) | attw logits(48)]
__device__ float g_ms[MQ*DIM];
__device__ float g_gnstat[16*2];          // per (b,group): mean, rstd
__device__ float g_part[16*32*2];         // partial sums for GN stats

__device__ __forceinline__ float gelu_f(float x) {
    return 0.5f * x * (1.0f + erff(x * 0.70710678118654752440f));
}

// ---------------- weight fusion: Wv = pv_w@vp_w, Wo = op_w@po_w, Wsa=[so|aw] --
__global__ void prep_kernel(const float* __restrict__ pv_w, const float* __restrict__ pv_b,
                            const float* __restrict__ vp_w, const float* __restrict__ vp_b,
                            const float* __restrict__ op_w, const float* __restrict__ op_b,
                            const float* __restrict__ po_w, const float* __restrict__ po_b,
                            const float* __restrict__ so_w, const float* __restrict__ so_b,
                            const float* __restrict__ aw_w, const float* __restrict__ aw_b) {
    int r = blockIdx.x;      // 0..255
    int d = threadIdx.x;     // 0..127
    float acc = 0.f;
    for (int k = 0; k < 128; k++) acc += pv_w[r*128+k] * vp_w[k*128+d];
    g_Wv[r*128+d] = acc;
    if (r < 128) {
        float a2 = 0.f;
        for (int k = 0; k < 128; k++) a2 += op_w[r*128+k] * po_w[k*128+d];
        g_Wo[r*128+d] = a2;
        for (int n = d; n < 144; n += 128)
            g_Wsa[r*144+n] = (n < 96) ? so_w[r*96+n] : aw_w[r*48 + (n-96)];
    }
    if (r == 0) {
        float bv = 0.f, bo = 0.f;
        for (int k = 0; k < 128; k++) { bv += pv_b[k]*vp_w[k*128+d]; bo += op_b[k]*po_w[k*128+d]; }
        g_bv[d] = bv + vp_b[d];
        g_bo[d] = bo + po_b[d];
        for (int n = d; n < 144; n += 128)
            g_bsa[n] = (n < 96) ? so_b[n] : aw_b[n-96];
    }
}

// ---------------- generic tiled GEMM: C[M,N] = act(A@W + bias + ext) ----------
// A element (m,k) at A[m*a_ms + k*a_ks]   (handles row-major and bev-transposed)
// ext_mode: 0 none, 1 azimuth(sin,cos at W rows K,K+1), 2 two floats from ext[m]
__global__ __launch_bounds__(256) void gemm_kernel(
    const float* __restrict__ A, long long a_ms, long long a_ks, long long a_bstride,
    const float* __restrict__ W, int ldw,
    const float* __restrict__ bias,
    float* __restrict__ C, long long c_bstride,
    int M, int K, int N,
    int ext_mode, const float* __restrict__ ext, int act_gelu)
{
    __shared__ float As[16][65];
    __shared__ float Ws[16][64];
    __shared__ float We[2][64];
    const float* Ab = A + (long long)blockIdx.z * a_bstride;
    float* Cb = C + (long long)blockIdx.z * c_bstride;
    int m0 = blockIdx.x * 64, n0 = blockIdx.y * 64;
    int tid = threadIdx.x;
    int tm = (tid >> 4) * 4, tn = (tid & 15) * 4;
    float acc[4][4] = {};
    bool akm = (a_ks == 1);
    for (int k0 = 0; k0 < K; k0 += 16) {
        for (int t = tid; t < 64*16; t += 256) {
            int m, k;
            if (akm) { m = t >> 4; k = t & 15; }
            else     { k = t >> 6; m = t & 63; }
            int gm = m0 + m, gk = k0 + k;
            As[k][m] = (gm < M && gk < K) ? Ab[(long long)gm*a_ms + (long long)gk*a_ks] : 0.f;
        }
        for (int t = tid; t < 16*64; t += 256) {
            int k = t >> 6, n = t & 63;
            int gk = k0 + k, gn = n0 + n;
            Ws[k][n] = (gk < K && gn < N) ? W[gk*ldw + gn] : 0.f;
        }
        __syncthreads();
        #pragma unroll
        for (int k = 0; k < 16; k++) {
            float a0 = As[k][tm], a1 = As[k][tm+1], a2 = As[k][tm+2], a3 = As[k][tm+3];
            float4 w = *(const float4*)&Ws[k][tn];
            acc[0][0] += a0*w.x; acc[0][1] += a0*w.y; acc[0][2] += a0*w.z; acc[0][3] += a0*w.w;
            acc[1][0] += a1*w.x; acc[1][1] += a1*w.y; acc[1][2] += a1*w.z; acc[1][3] += a1*w.w;
            acc[2][0] += a2*w.x; acc[2][1] += a2*w.y; acc[2][2] += a2*w.z; acc[2][3] += a2*w.w;
            acc[3][0] += a3*w.x; acc[3][1] += a3*w.y; acc[3][2] += a3*w.z; acc[3][3] += a3*w.w;
        }
        __syncthreads();
    }
    if (ext_mode) {
        for (int t = tid; t < 2*64; t += 256) {
            int e = t >> 6, n = t & 63;
            int gn = n0 + n;
            We[e][n] = (gn < N) ? W[(K+e)*ldw + gn] : 0.f;
        }
        __syncthreads();
    }
    #pragma unroll
    for (int i = 0; i < 4; i++) {
        int gm = m0 + tm + i;
        if (gm >= M) continue;
        float e0 = 0.f, e1 = 0.f;
        if (ext_mode == 1) {
            int j = gm & (WRV_ - 1);
            float az = -3.14159265358979323846f + (float)j * (6.28318530717958647693f / (float)WRV_);
            e0 = sinf(az); e1 = cosf(az);
        } else if (ext_mode == 2) {
            e0 = ext[gm*2]; e1 = ext[gm*2+1];
        }
        #pragma unroll
        for (int jn = 0; jn < 4; jn++) {
            int gn = n0 + tn + jn;
            if (gn >= N) continue;
            float v = acc[i][jn] + bias[gn];
            if (ext_mode) v += e0*We[0][tn+jn] + e1*We[1][tn+jn];
            if (act_gelu) v = gelu_f(v);
            Cb[(long long)gm*N + gn] = v;
        }
    }
}

// ---------------- group-norm stats (two stage) --------------------------------
__global__ void gn_partial(const float* __restrict__ x, int C, int cg,
                           int rowsPerB, int rowsPerChunk) {
    int g = blockIdx.x, b = blockIdx.y, ch = blockIdx.z;
    int G = gridDim.x;
    const float* xb = x + ((long long)b*rowsPerB + (long long)ch*rowsPerChunk)*C;
    int total = rowsPerChunk * cg;
    float s = 0.f, s2 = 0.f;
    for (int t = threadIdx.x; t < total; t += blockDim.x) {
        int r = t / cg, c = g*cg + (t - (t/cg)*cg);
        float v = xb[(long long)r*C + c];
        s += v; s2 += v*v;
    }
    __shared__ float sh[256], sh2[256];
    sh[threadIdx.x] = s; sh2[threadIdx.x] = s2;
    __syncthreads();
    for (int off = 128; off > 0; off >>= 1) {
        if (threadIdx.x < off) { sh[threadIdx.x] += sh[threadIdx.x+off]; sh2[threadIdx.x] += sh2[threadIdx.x+off]; }
        __syncthreads();
    }
    if (threadIdx.x == 0) {
        int idx = ((b*G + g)*32 + ch)*2;
        g_part[idx] = sh[0]; g_part[idx+1] = sh2[0];
    }
}

__global__ void gn_finalize(int total) {   // grid = B*G blocks of 32 threads
    int bg = blockIdx.x, lane = threadIdx.x;
    float s = g_part[(bg*32+lane)*2], s2 = g_part[(bg*32+lane)*2+1];
    for (int off = 16; off; off >>= 1) {
        s  += __shfl_down_sync(0xffffffffu, s,  off);
        s2 += __shfl_down_sync(0xffffffffu, s2, off);
    }
    if (lane == 0) {
        float mean = s / (float)total;
        float var = s2 / (float)total - mean*mean;
        g_gnstat[bg*2]   = mean;
        g_gnstat[bg*2+1] = rsqrtf(var + 1e-5f);
    }
}

// GN1 apply + GELU (in place)
__global__ void gn_apply(float* __restrict__ x, const float* __restrict__ gamma,
                         const float* __restrict__ beta, int C, int cg, int rowsPerB, int G) {
    long long idx = (long long)blockIdx.x * blockDim.x + threadIdx.x;
    long long total = (long long)MQ * C;
    if (idx >= total) return;
    int c = (int)(idx % C);
    long long m = idx / C;
    int b = (int)(m / rowsPerB);
    int g = c / cg;
    float mean = g_gnstat[(b*G+g)*2], rstd = g_gnstat[(b*G+g)*2+1];
    float v = (x[idx] - mean) * rstd * gamma[c] + beta[c];
    x[idx] = gelu_f(v);
}

// ---------------- 3x3 circular conv, 128 -> 64 ch -----------------------------
#define CTI 4
#define CTJ 32
#define CCT 32
#define SPITCH 33
#define CONV_SIN  (6*34*SPITCH)        // 6732 floats
#define CONV_SW   (9*CCT*64)           // 18432 floats
#define CONV_SMEM ((CONV_SIN + CONV_SW)*4)

__global__ __launch_bounds__(256) void conv3x3_kernel(
    const float* __restrict__ hin, const float* __restrict__ w2, float* __restrict__ hout)
{
    extern __shared__ float smem[];
    float* sIn = smem;
    float* sW  = smem + CONV_SIN;
    int bj = blockIdx.x, bi = blockIdx.y, b = blockIdx.z;
    int tid = threadIdx.x;
    int lane = tid & 31, wid = tid >> 5;
    int oc_base = wid * 8;
    float acc[4][8];
    #pragma unroll
    for (int u = 0; u < 4; u++)
        #pragma unroll
        for (int o = 0; o < 8; o++) acc[u][o] = 0.f;

    for (int ct = 0; ct < 128; ct += CCT) {
        __syncthreads();
        // stage input patch [6 rows][34 cols][32 ch] with circular wrap
        for (int t = tid; t < 6*34*CCT; t += 256) {
            int li = t / (34*CCT);
            int rem = t - li*(34*CCT);
            int lj = rem / CCT;
            int cc = rem - lj*CCT;
            int gi = (bi*CTI + li - 1 + HRV_) & (HRV_ - 1);
            int gj = (bj*CTJ + lj - 1 + WRV_) & (WRV_ - 1);
            sIn[(li*34 + lj)*SPITCH + cc] =
                hin[(((long long)b*HRV_ + gi)*WRV_ + gj)*128 + ct + cc];
        }
        // stage weight chunk [9][32 ic][64 oc]
        for (int t = tid; t < 9*CCT*64; t += 256) {
            int rc = t / (CCT*64);
            int rem = t - rc*(CCT*64);
            int ic = rem >> 6;
            int oc = rem & 63;
            sW[t] = w2[((long long)rc*128 + ct + ic)*64 + oc];
        }
        __syncthreads();
        #pragma unroll
        for (int rc = 0; rc < 9; rc++) {
            int r = rc / 3, c = rc - r*3;
            const float* wr = sW + rc*CCT*64 + oc_base;
            const float* ir = sIn + (r*34 + lane + c)*SPITCH;
            #pragma unroll 4
            for (int cc = 0; cc < CCT; cc++) {
                float4 wa = *(const float4*)(wr + cc*64);
                float4 wb = *(const float4*)(wr + cc*64 + 4);
                float iv[4];
                #pragma unroll
                for (int u = 0; u < 4; u++) iv[u] = ir[u*(34*SPITCH) + cc];
                #pragma unroll
                for (int u = 0; u < 4; u++) {
                    acc[u][0] += iv[u]*wa.x; acc[u][1] += iv[u]*wa.y;
                    acc[u][2] += iv[u]*wa.z; acc[u][3] += iv[u]*wa.w;
                    acc[u][4] += iv[u]*wb.x; acc[u][5] += iv[u]*wb.y;
                    acc[u][6] += iv[u]*wb.z; acc[u][7] += iv[u]*wb.w;
                }
            }
        }
    }
    #pragma unroll
    for (int u = 0; u < 4; u++) {
        long long o = (((long long)b*HRV_ + bi*CTI + u)*WRV_ + bj*CTJ + lane)*64 + oc_base;
        float4 v0 = make_float4(acc[u][0], acc[u][1], acc[u][2], acc[u][3]);
        float4 v1 = make_float4(acc[u][4], acc[u][5], acc[u][6], acc[u][7]);
        *(float4*)(hout + o)     = v0;
        *(float4*)(hout + o + 4) = v1;
    }
}

// ---------------- GN2 + GELU + rh3 head + reference points --------------------
__global__ __launch_bounds__(128) void rh_final_kernel(
    const float* __restrict__ h2, const float* __restrict__ g2, const float* __restrict__ be2,
    const float* __restrict__ w3, const float* __restrict__ b3)
{
    __shared__ float sh[128*65];
    int m0 = blockIdx.x * 128;
    for (int t = threadIdx.x; t < 128*64; t += 128) {
        int r = t >> 6, c = t & 63;
        sh[r*65 + c] = h2[(long long)(m0 + r)*64 + c];
    }
    __syncthreads();
    int m = m0 + threadIdx.x;
    int b = m >> 15;   // /32768
    const float* row = &sh[threadIdx.x*65];
    float mu = 0.f, ls = 0.f;
    #pragma unroll
    for (int c = 0; c < 64; c++) {
        int g = c >> 3;
        float mean = g_gnstat[(b*8+g)*2], rstd = g_gnstat[(b*8+g)*2+1];
        float v = (row[c] - mean) * rstd * g2[c] + be2[c];
        v = gelu_f(v);
        mu += v * w3[c*2];
        ls += v * w3[c*2+1];
    }
    mu += b3[0]; ls += b3[1];
    mu = fminf(fmaxf(mu, 0.f), 55.f);
    ls = fminf(fmaxf(ls, -5.f), 3.f);
    float sig = expf(ls);
    g_sigfeat[m*2]   = ls;
    g_sigfeat[m*2+1] = 1.f / (sig + 1e-6f);
    int j = m & (WRV_ - 1);
    float az = -3.14159265358979323846f + (float)j * (6.28318530717958647693f / (float)WRV_);
    float xmu = mu * cosf(az), ymu = mu * sinf(az);
    float rx = fminf(fmaxf((xmu + 50.f) * 0.01f, 0.f), 1.f);
    float ry = fminf(fmaxf((ymu + 50.f) * 0.01f, 0.f), 1.f);
    g_refpx[m*2]   = rx * (float)WB_ - 0.5f;
    g_refpx[m*2+1] = ry * (float)HB_ - 0.5f;
}

// ---------------- MSDA: softmax + bilinear gather + weighted sum --------------
__global__ __launch_bounds__(256) void msda_kernel() {
    __shared__ float s[8][160];
    int wid = threadIdx.x >> 5, lane = threadIdx.x & 31;
    int m = blockIdx.x * 8 + wid;
    int b = m >> 15;
    float* sr = s[wid];
    for (int t = lane; t < 144; t += 32) sr[t] = g_sa[(long long)m*144 + t];
    __syncwarp();
    if (lane < NHEADS) {
        float mx = -1e30f;
        #pragma unroll
        for (int p = 0; p < NPTS; p++) mx = fmaxf(mx, sr[96 + lane*NPTS + p]);
        float e[NPTS], sum = 0.f;
        #pragma unroll
        for (int p = 0; p < NPTS; p++) { e[p] = expf(sr[96 + lane*NPTS + p] - mx); sum += e[p]; }
        float inv = 1.f / sum;
        #pragma unroll
        for (int p = 0; p < NPTS; p++) sr[96 + lane*NPTS + p] = e[p] * inv;
    }
    __syncwarp();
    float pxb = g_refpx[m*2], pyb = g_refpx[m*2+1];
    int grp = lane >> 4, k = lane & 15;
    const float* val = g_value + (long long)b*NV_*DIM;
    float acc[NHEADS];
    #pragma unroll
    for (int h = 0; h < NHEADS; h++) acc[h] = 0.f;
    #pragma unroll
    for (int h = 0; h < NHEADS; h++) {
        const float* vh = val + h*16 + k;
        #pragma unroll
        for (int pp = 0; pp < 3; pp++) {
            int p = pp*2 + grp;
            float ox = sr[h*12 + p*2], oy = sr[h*12 + p*2 + 1];
            float aw = sr[96 + h*NPTS + p];
            float px = pxb + ox, py = pyb + oy;
            float fx = floorf(px), fy = floorf(py);
            int x0 = (int)fx, y0 = (int)fy;
            float wx = px - fx, wy = py - fy;
            bool xv0 = (x0 >= 0) && (x0 < WB_);
            bool xv1 = (x0 + 1 >= 0) && (x0 + 1 < WB_);
            float v = 0.f;
            if (y0 >= 0 && y0 < HB_) {
                const float* row0 = vh + (long long)y0*WB_*DIM;
                if (xv0) v += (1.f-wx)*(1.f-wy) * row0[(long long)x0*DIM];
                if (xv1) v += wx*(1.f-wy)       * row0[(long long)(x0+1)*DIM];
            }
            if (y0 + 1 >= 0 && y0 + 1 < HB_) {
                const float* row1 = vh + (long long)(y0+1)*WB_*DIM;
                if (xv0) v += (1.f-wx)*wy * row1[(long long)x0*DIM];
                if (xv1) v += wx*wy       * row1[(long long)(x0+1)*DIM];
            }
            acc[h] += aw * v;
        }
    }
    #pragma unroll
    for (int h = 0; h < NHEADS; h++) acc[h] += __shfl_xor_sync(0xffffffffu, acc[h], 16);
    if (lane < 16) {
        #pragma unroll
        for (int h = 0; h < NHEADS; h++) g_ms[(long long)m*DIM + h*16 + k] = acc[h];
    }
}

// ---------------- host driver -------------------------------------------------
extern "C" void kernel_launch(void* const* d_in, const int* in_sizes, int n_in,
                              void* d_out, int out_size) {
    const float* x_rv   = (const float*)d_in[0];
    const float* bev    = (const float*)d_in[1];
    const float* pq_w   = (const float*)d_in[2];
    const float* pq_b   = (const float*)d_in[3];
    const float* pv_w   = (const float*)d_in[4];
    const float* pv_b   = (const float*)d_in[5];
    const float* po_w   = (const float*)d_in[6];
    const float* po_b   = (const float*)d_in[7];
    const float* qs_w1  = (const float*)d_in[8];
    const float* qs_b1  = (const float*)d_in[9];
    const float* qs_w2  = (const float*)d_in[10];
    const float* qs_b2  = (const float*)d_in[11];
    const float* rh_w1  = (const float*)d_in[12];
    const float* rh_b1  = (const float*)d_in[13];
    const float* rh_g1  = (const float*)d_in[14];
    const float* rh_be1 = (const float*)d_in[15];
    const float* rh_w2  = (const float*)d_in[16];
    const float* rh_g2  = (const float*)d_in[17];
    const float* rh_be2 = (const float*)d_in[18];
    const float* rh_w3  = (const float*)d_in[19];
    const float* rh_b3  = (const float*)d_in[20];
    // so_w/so_b/aw_w/aw_b consumed by prep_kernel (d_in[21..24])
    const float* so_w   = (const float*)d_in[21];
    const float* so_b   = (const float*)d_in[22];
    const float* aw_w   = (const float*)d_in[23];
    const float* aw_b   = (const float*)d_in[24];
    const float* vp_w   = (const float*)d_in[25];
    const float* vp_b   = (const float*)d_in[26];
    const float* op_w   = (const float*)d_in[27];
    const float* op_b   = (const float*)d_in[28];
    float* out = (float*)d_out;

    float *p_value, *p_Q0, *p_h1, *p_h2, *p_q1, *p_query, *p_sa, *p_ms, *p_sigfeat;
    float *p_Wv, *p_bv, *p_Wo, *p_bo, *p_Wsa, *p_bsa;
    cudaGetSymbolAddress((void**)&p_value,   g_value);
    cudaGetSymbolAddress((void**)&p_Q0,      g_Q0);
    cudaGetSymbolAddress((void**)&p_h1,      g_h1);
    cudaGetSymbolAddress((void**)&p_h2,      g_h2);
    cudaGetSymbolAddress((void**)&p_q1,      g_q1);
    cudaGetSymbolAddress((void**)&p_query,   g_query);
    cudaGetSymbolAddress((void**)&p_sa,      g_sa);
    cudaGetSymbolAddress((void**)&p_ms,      g_ms);
    cudaGetSymbolAddress((void**)&p_sigfeat, g_sigfeat);
    cudaGetSymbolAddress((void**)&p_Wv,      g_Wv);
    cudaGetSymbolAddress((void**)&p_bv,      g_bv);
    cudaGetSymbolAddress((void**)&p_Wo,      g_Wo);
    cudaGetSymbolAddress((void**)&p_bo,      g_bo);
    cudaGetSymbolAddress((void**)&p_Wsa,     g_Wsa);
    cudaGetSymbolAddress((void**)&p_bsa,     g_bsa);

    cudaFuncSetAttribute(conv3x3_kernel, cudaFuncAttributeMaxDynamicSharedMemorySize, CONV_SMEM);

    // 1. fuse weights
    prep_kernel<<<256, 128>>>(pv_w, pv_b, vp_w, vp_b, op_w, op_b, po_w, po_b,
                              so_w, so_b, aw_w, aw_b);

    // 2. value = bev^T @ Wv + bv  (M=40000/batch, K=256, A is k-strided)
    gemm_kernel<<<dim3(625, 2, 2), 256>>>(bev, 1LL, (long long)NV_, (long long)CB_*NV_,
                                          p_Wv, DIM, p_bv,
                                          p_value, (long long)NV_*DIM,
                                          NV_, CB_, DIM, 0, nullptr, 0);

    // 3. Q0 = x_rv @ pq_w + pq_b
    gemm_kernel<<<dim3(1024, 2, 1), 256>>>(x_rv, (long long)CRV_, 1LL, 0LL,
                                           pq_w, DIM, pq_b,
                                           p_Q0, 0LL, MQ, CRV_, DIM, 0, nullptr, 0);

    // 4. h1 = [x_rv | sin az | cos az] @ rh_w1 + rh_b1   (azimuth analytic)
    gemm_kernel<<<dim3(1024, 2, 1), 256>>>(x_rv, (long long)CRV_, 1LL, 0LL,
                                           rh_w1, DIM, rh_b1,
                                           p_h1, 0LL, MQ, CRV_, DIM, 1, nullptr, 0);

    // 5. GN1 stats + apply + GELU (in place on h1)
    gn_partial<<<dim3(8, B_, 32), 256>>>(p_h1, 128, 16, NQPB, NQPB/32);
    gn_finalize<<<16, 32>>>(NQPB * 16);
    gn_apply<<<(MQ*128)/256, 256>>>(p_h1, rh_g1, rh_be1, 128, 16, NQPB, 8);

    // 6. 3x3 circular conv 128->64
    conv3x3_kernel<<<dim3(WRV_/CTJ, HRV_/CTI, B_), 256, CONV_SMEM>>>(p_h1, rh_w2, p_h2);

    // 7. GN2 stats, then fused GN2+GELU+rh3 head (mu/log_sigma/ref/sig_feat)
    gn_partial<<<dim3(8, B_, 32), 256>>>(p_h2, 64, 8, NQPB, NQPB/32);
    gn_finalize<<<16, 32>>>(NQPB * 8);
    rh_final_kernel<<<MQ/128, 128>>>(p_h2, rh_g2, rh_be2, rh_w3, rh_b3);

    // 8. q1 = gelu([Q0 | sig_feat] @ qs_w1 + qs_b1)
    gemm_kernel<<<dim3(1024, 2, 1), 256>>>(p_Q0, (long long)DIM, 1LL, 0LL,
                                           qs_w1, DIM, qs_b1,
                                           p_q1, 0LL, MQ, DIM, DIM, 2, p_sigfeat, 1);

    // 9. query = q1 @ qs_w2 + qs_b2
    gemm_kernel<<<dim3(1024, 2, 1), 256>>>(p_q1, (long long)DIM, 1LL, 0LL,
                                           qs_w2, DIM, qs_b2,
                                           p_query, 0LL, MQ, DIM, DIM, 0, nullptr, 0);

    // 10. sampling offsets + attention logits: query @ [so_w | aw_w]
    gemm_kernel<<<dim3(1024, 3, 1), 256>>>(p_query, (long long)DIM, 1LL, 0LL,
                                           p_Wsa, 144, p_bsa,
                                           p_sa, 0LL, MQ, DIM, 144, 0, nullptr, 0);

    // 11. MSDA gather
    msda_kernel<<<MQ/8, 256>>>();

    // 12. y = ms @ (op_w@po_w) + fused bias  -> d_out
    gemm_kernel<<<dim3(1024, 2, 1), 256>>>(p_ms, (long long)DIM, 1LL, 0LL,
                                           p_Wo, DIM, p_bo,
                                           out, 0LL, MQ, DIM, DIM, 0, nullptr, 0);
}

// round 3
// speedup vs baseline: 1.1968x; 1.1968x over previous
#include <cuda_runtime.h>
#include <cuda_bf16.h>
#include <math.h>

#define B_   2
#define HRV_ 32
#define WRV_ 1024
#define NQPB 32768
#define MQ   65536
#define CRV_ 64
#define CB_  256
#define HB_  200
#define WB_  200
#define NV_  40000
#define DIM  128
#define NHEADS 8
#define NPTS 6

// ---------------- scratch (device globals; no allocation allowed) -------------
__device__ float g_Wv[CB_*DIM];
__device__ float g_bv[DIM];
__device__ float g_Wo[DIM*DIM];
__device__ float g_bo[DIM];
__device__ float g_Wsa[DIM*144];
__device__ float g_bsa[144];
__device__ float g_value[B_*NV_*DIM];     // [b, y*200+x, 128]
__device__ float g_Q0[MQ*DIM];
__device__ float g_h1[MQ*DIM];            // raw h1 (GN1+GELU applied in conv staging)
__device__ float g_h2[MQ*64];
__device__ float g_q1[MQ*DIM];
__device__ float g_query[MQ*DIM];
__device__ float g_sigfeat[MQ*2];
__device__ float g_refpx[MQ*2];           // rx*200-0.5, ry*200-0.5
__device__ float g_sa[MQ*144];            // [offs(96) | attw logits(48)]
__device__ float g_ms[MQ*DIM];
__device__ float g_gnstat[16*2];          // per (b,group): mean, rstd
__device__ float g_part[16*32*2];         // partial sums for GN stats

__device__ __forceinline__ float gelu_f(float x) {
    return 0.5f * x * (1.0f + erff(x * 0.70710678118654752440f));
}

// ---------------- weight fusion: Wv = pv_w@vp_w, Wo = op_w@po_w, Wsa=[so|aw] --
__global__ void prep_kernel(const float* __restrict__ pv_w, const float* __restrict__ pv_b,
                            const float* __restrict__ vp_w, const float* __restrict__ vp_b,
                            const float* __restrict__ op_w, const float* __restrict__ op_b,
                            const float* __restrict__ po_w, const float* __restrict__ po_b,
                            const float* __restrict__ so_w, const float* __restrict__ so_b,
                            const float* __restrict__ aw_w, const float* __restrict__ aw_b) {
    int r = blockIdx.x;      // 0..255
    int d = threadIdx.x;     // 0..127
    float acc = 0.f;
    for (int k = 0; k < 128; k++) acc += pv_w[r*128+k] * vp_w[k*128+d];
    g_Wv[r*128+d] = acc;
    if (r < 128) {
        float a2 = 0.f;
        for (int k = 0; k < 128; k++) a2 += op_w[r*128+k] * po_w[k*128+d];
        g_Wo[r*128+d] = a2;
        for (int n = d; n < 144; n += 128)
            g_Wsa[r*144+n] = (n < 96) ? so_w[r*96+n] : aw_w[r*48 + (n-96)];
    }
    if (r == 0) {
        float bv = 0.f, bo = 0.f;
        for (int k = 0; k < 128; k++) { bv += pv_b[k]*vp_w[k*128+d]; bo += op_b[k]*po_w[k*128+d]; }
        g_bv[d] = bv + vp_b[d];
        g_bo[d] = bo + po_b[d];
        for (int n = d; n < 144; n += 128)
            g_bsa[n] = (n < 96) ? so_b[n] : aw_b[n-96];
    }
}

// ---------------- tiled GEMM: C[M,N] = act(A@W + bias + ext) ------------------
// 128x128 block tile, 8x8 per-thread register tile, BK=16.
// A element (m,k) at A[m*a_ms + k*a_ks]   (row-major: a_ks==1; bev: a_ms==1)
// ext_mode: 0 none, 1 azimuth(sin,cos at W rows K,K+1), 2 two floats from ext[m]
#define BM 128
#define BN 128
#define BK 16
#define APITCH (BM + 4)

__global__ __launch_bounds__(256, 2) void gemm_kernel(
    const float* __restrict__ A, long long a_ms, long long a_ks, long long a_bstride,
    const float* __restrict__ W, int ldw,
    const float* __restrict__ bias,
    float* __restrict__ C, long long c_bstride,
    int M, int K, int N,
    int ext_mode, const float* __restrict__ ext, int act_gelu)
{
    __shared__ float As[BK][APITCH];
    __shared__ float Ws[BK][BN];
    __shared__ float We[2][BN];
    const float* Ab = A + (long long)blockIdx.z * a_bstride;
    float* Cb = C + (long long)blockIdx.z * c_bstride;
    int m0 = blockIdx.x * BM, n0 = blockIdx.y * BN;
    int tid = threadIdx.x;
    int tm = (tid >> 4) * 8, tn = (tid & 15) * 8;
    float acc[8][8] = {};
    bool akm = (a_ks == 1);

    for (int k0 = 0; k0 < K; k0 += BK) {
        if (akm) {
            // row-major A: 128 rows x 16 k, float4 per thread x2
            #pragma unroll
            for (int t = tid; t < BM*BK/4; t += 256) {
                int m = t >> 2;
                int kk = (t & 3) * 4;
                int gm = m0 + m;
                float4 v = make_float4(0.f, 0.f, 0.f, 0.f);
                if (gm < M) v = *(const float4*)&Ab[(long long)gm*a_ms + (k0 + kk)];
                As[kk  ][m] = v.x;
                As[kk+1][m] = v.y;
                As[kk+2][m] = v.z;
                As[kk+3][m] = v.w;
            }
        } else {
            // m-contiguous A (bev^T): direct coalesced
            #pragma unroll
            for (int t = tid; t < BK*BM; t += 256) {
                int k = t >> 7, m = t & 127;
                int gm = m0 + m;
                As[k][m] = (gm < M) ? Ab[(long long)(k0 + k)*a_ks + gm] : 0.f;
            }
        }
        #pragma unroll
        for (int t = tid; t < BK*BN/4; t += 256) {
            int k = t >> 5;
            int n = (t & 31) * 4;
            int gn = n0 + n;
            float4 v = make_float4(0.f, 0.f, 0.f, 0.f);
            if (gn < N) v = *(const float4*)&W[(long long)(k0 + k)*ldw + gn];
            *(float4*)&Ws[k][n] = v;
        }
        __syncthreads();
        #pragma unroll
        for (int k = 0; k < BK; k++) {
            float4 a0 = *(const float4*)&As[k][tm];
            float4 a1 = *(const float4*)&As[k][tm+4];
            float4 w0 = *(const float4*)&Ws[k][tn];
            float4 w1 = *(const float4*)&Ws[k][tn+4];
            float av[8] = {a0.x, a0.y, a0.z, a0.w, a1.x, a1.y, a1.z, a1.w};
            float wv[8] = {w0.x, w0.y, w0.z, w0.w, w1.x, w1.y, w1.z, w1.w};
            #pragma unroll
            for (int i = 0; i < 8; i++)
                #pragma unroll
                for (int j = 0; j < 8; j++)
                    acc[i][j] += av[i] * wv[j];
        }
        __syncthreads();
    }
    if (ext_mode) {
        for (int t = tid; t < 2*BN; t += 256) {
            int e = t >> 7, n = t & 127;
            int gn = n0 + n;
            We[e][n] = (gn < N) ? W[(long long)(K+e)*ldw + gn] : 0.f;
        }
        __syncthreads();
    }
    #pragma unroll
    for (int i = 0; i < 8; i++) {
        int gm = m0 + tm + i;
        if (gm >= M) continue;
        float e0 = 0.f, e1 = 0.f;
        if (ext_mode == 1) {
            int j = gm & (WRV_ - 1);
            float az = -3.14159265358979323846f + (float)j * (6.28318530717958647693f / (float)WRV_);
            e0 = sinf(az); e1 = cosf(az);
        } else if (ext_mode == 2) {
            e0 = ext[gm*2]; e1 = ext[gm*2+1];
        }
        float o[8];
        #pragma unroll
        for (int jn = 0; jn < 8; jn++) {
            int gn = n0 + tn + jn;
            float v = acc[i][jn];
            if (gn < N) {
                v += bias[gn];
                if (ext_mode) v += e0*We[0][tn+jn] + e1*We[1][tn+jn];
                if (act_gelu) v = gelu_f(v);
            }
            o[jn] = v;
        }
        long long base = (long long)gm*N + n0 + tn;
        if (n0 + tn < N)     *(float4*)&Cb[base]     = make_float4(o[0], o[1], o[2], o[3]);
        if (n0 + tn + 4 < N) *(float4*)&Cb[base + 4] = make_float4(o[4], o[5], o[6], o[7]);
    }
}

// ---------------- group-norm stats (two stage) --------------------------------
__global__ void gn_partial(const float* __restrict__ x, int C, int cg,
                           int rowsPerB, int rowsPerChunk) {
    int g = blockIdx.x, b = blockIdx.y, ch = blockIdx.z;
    int G = gridDim.x;
    const float* xb = x + ((long long)b*rowsPerB + (long long)ch*rowsPerChunk)*C;
    int total = rowsPerChunk * cg;
    float s = 0.f, s2 = 0.f;
    for (int t = threadIdx.x; t < total; t += blockDim.x) {
        int r = t / cg, c = g*cg + (t - (t/cg)*cg);
        float v = xb[(long long)r*C + c];
        s += v; s2 += v*v;
    }
    __shared__ float sh[256], sh2[256];
    sh[threadIdx.x] = s; sh2[threadIdx.x] = s2;
    __syncthreads();
    for (int off = 128; off > 0; off >>= 1) {
        if (threadIdx.x < off) { sh[threadIdx.x] += sh[threadIdx.x+off]; sh2[threadIdx.x] += sh2[threadIdx.x+off]; }
        __syncthreads();
    }
    if (threadIdx.x == 0) {
        int idx = ((b*G + g)*32 + ch)*2;
        g_part[idx] = sh[0]; g_part[idx+1] = sh2[0];
    }
}

__global__ void gn_finalize(int total) {   // grid = B*G blocks of 32 threads
    int bg = blockIdx.x, lane = threadIdx.x;
    float s = g_part[(bg*32+lane)*2], s2 = g_part[(bg*32+lane)*2+1];
    for (int off = 16; off; off >>= 1) {
        s  += __shfl_down_sync(0xffffffffu, s,  off);
        s2 += __shfl_down_sync(0xffffffffu, s2, off);
    }
    if (lane == 0) {
        float mean = s / (float)total;
        float var = s2 / (float)total - mean*mean;
        g_gnstat[bg*2]   = mean;
        g_gnstat[bg*2+1] = rsqrtf(var + 1e-5f);
    }
}

// ---------------- 3x3 circular conv, 128 -> 64 ch, GN1+GELU fused in staging --
#define CTI 4
#define CTJ 32
#define CCT 32
#define SPITCH 33
#define CONV_SIN  (6*34*SPITCH)        // 6732 floats
#define CONV_SW   (9*CCT*64)           // 18432 floats
#define CONV_SMEM ((CONV_SIN + CONV_SW)*4)

__global__ __launch_bounds__(256) void conv3x3_kernel(
    const float* __restrict__ hin, const float* __restrict__ w2, float* __restrict__ hout,
    const float* __restrict__ g1, const float* __restrict__ be1)
{
    extern __shared__ float smem[];
    float* sIn = smem;
    float* sW  = smem + CONV_SIN;
    int bj = blockIdx.x, bi = blockIdx.y, b = blockIdx.z;
    int tid = threadIdx.x;
    int lane = tid & 31, wid = tid >> 5;
    int oc_base = wid * 8;
    float acc[4][8];
    #pragma unroll
    for (int u = 0; u < 4; u++)
        #pragma unroll
        for (int o = 0; o < 8; o++) acc[u][o] = 0.f;

    for (int ct = 0; ct < 128; ct += CCT) {
        __syncthreads();
        // stage input patch [6 rows][34 cols][32 ch] with circular wrap; apply GN1+GELU
        for (int t = tid; t < 6*34*CCT; t += 256) {
            int li = t / (34*CCT);
            int rem = t - li*(34*CCT);
            int lj = rem / CCT;
            int cc = rem - lj*CCT;
            int gi = (bi*CTI + li - 1 + HRV_) & (HRV_ - 1);
            int gj = (bj*CTJ + lj - 1 + WRV_) & (WRV_ - 1);
            int c  = ct + cc;
            float v = hin[(((long long)b*HRV_ + gi)*WRV_ + gj)*128 + c];
            int g = c >> 4;
            float mean = g_gnstat[(b*8+g)*2], rstd = g_gnstat[(b*8+g)*2+1];
            sIn[(li*34 + lj)*SPITCH + cc] = gelu_f((v - mean)*rstd*g1[c] + be1[c]);
        }
        // stage weight chunk [9][32 ic][64 oc]
        for (int t = tid; t < 9*CCT*64; t += 256) {
            int rc = t / (CCT*64);
            int rem = t - rc*(CCT*64);
            int ic = rem >> 6;
            int oc = rem & 63;
            sW[t] = w2[((long long)rc*128 + ct + ic)*64 + oc];
        }
        __syncthreads();
        #pragma unroll
        for (int rc = 0; rc < 9; rc++) {
            int r = rc / 3, c = rc - r*3;
            const float* wr = sW + rc*CCT*64 + oc_base;
            const float* ir = sIn + (r*34 + lane + c)*SPITCH;
            #pragma unroll 4
            for (int cc = 0; cc < CCT; cc++) {
                float4 wa = *(const float4*)(wr + cc*64);
                float4 wb = *(const float4*)(wr + cc*64 + 4);
                float iv[4];
                #pragma unroll
                for (int u = 0; u < 4; u++) iv[u] = ir[u*(34*SPITCH) + cc];
                #pragma unroll
                for (int u = 0; u < 4; u++) {
                    acc[u][0] += iv[u]*wa.x; acc[u][1] += iv[u]*wa.y;
                    acc[u][2] += iv[u]*wa.z; acc[u][3] += iv[u]*wa.w;
                    acc[u][4] += iv[u]*wb.x; acc[u][5] += iv[u]*wb.y;
                    acc[u][6] += iv[u]*wb.z; acc[u][7] += iv[u]*wb.w;
                }
            }
        }
    }
    #pragma unroll
    for (int u = 0; u < 4; u++) {
        long long o = (((long long)b*HRV_ + bi*CTI + u)*WRV_ + bj*CTJ + lane)*64 + oc_base;
        *(float4*)(hout + o)     = make_float4(acc[u][0], acc[u][1], acc[u][2], acc[u][3]);
        *(float4*)(hout + o + 4) = make_float4(acc[u][4], acc[u][5], acc[u][6], acc[u][7]);
    }
}

// ---------------- GN2 + GELU + rh3 head + reference points --------------------
__global__ __launch_bounds__(128) void rh_final_kernel(
    const float* __restrict__ h2, const float* __restrict__ g2, const float* __restrict__ be2,
    const float* __restrict__ w3, const float* __restrict__ b3)
{
    __shared__ float sh[128*65];
    int m0 = blockIdx.x * 128;
    for (int t = threadIdx.x; t < 128*64; t += 128) {
        int r = t >> 6, c = t & 63;
        sh[r*65 + c] = h2[(long long)(m0 + r)*64 + c];
    }
    __syncthreads();
    int m = m0 + threadIdx.x;
    int b = m >> 15;   // /32768
    const float* row = &sh[threadIdx.x*65];
    float mu = 0.f, ls = 0.f;
    #pragma unroll
    for (int c = 0; c < 64; c++) {
        int g = c >> 3;
        float mean = g_gnstat[(b*8+g)*2], rstd = g_gnstat[(b*8+g)*2+1];
        float v = (row[c] - mean) * rstd * g2[c] + be2[c];
        v = gelu_f(v);
        mu += v * w3[c*2];
        ls += v * w3[c*2+1];
    }
    mu += b3[0]; ls += b3[1];
    mu = fminf(fmaxf(mu, 0.f), 55.f);
    ls = fminf(fmaxf(ls, -5.f), 3.f);
    float sig = expf(ls);
    g_sigfeat[m*2]   = ls;
    g_sigfeat[m*2+1] = 1.f / (sig + 1e-6f);
    int j = m & (WRV_ - 1);
    float az = -3.14159265358979323846f + (float)j * (6.28318530717958647693f / (float)WRV_);
    float xmu = mu * cosf(az), ymu = mu * sinf(az);
    float rx = fminf(fmaxf((xmu + 50.f) * 0.01f, 0.f), 1.f);
    float ry = fminf(fmaxf((ymu + 50.f) * 0.01f, 0.f), 1.f);
    g_refpx[m*2]   = rx * (float)WB_ - 0.5f;
    g_refpx[m*2+1] = ry * (float)HB_ - 0.5f;
}

// ---------------- MSDA: softmax + bilinear gather + weighted sum --------------
__global__ __launch_bounds__(256) void msda_kernel() {
    __shared__ float s[8][160];
    int wid = threadIdx.x >> 5, lane = threadIdx.x & 31;
    int m = blockIdx.x * 8 + wid;
    int b = m >> 15;
    float* sr = s[wid];
    for (int t = lane; t < 144; t += 32) sr[t] = g_sa[(long long)m*144 + t];
    __syncwarp();
    if (lane < NHEADS) {
        float mx = -1e30f;
        #pragma unroll
        for (int p = 0; p < NPTS; p++) mx = fmaxf(mx, sr[96 + lane*NPTS + p]);
        float e[NPTS], sum = 0.f;
        #pragma unroll
        for (int p = 0; p < NPTS; p++) { e[p] = expf(sr[96 + lane*NPTS + p] - mx); sum += e[p]; }
        float inv = 1.f / sum;
        #pragma unroll
        for (int p = 0; p < NPTS; p++) sr[96 + lane*NPTS + p] = e[p] * inv;
    }
    __syncwarp();
    float pxb = g_refpx[m*2], pyb = g_refpx[m*2+1];
    int grp = lane >> 4, k = lane & 15;
    const float* val = g_value + (long long)b*NV_*DIM;
    float acc[NHEADS];
    #pragma unroll
    for (int h = 0; h < NHEADS; h++) acc[h] = 0.f;
    #pragma unroll
    for (int h = 0; h < NHEADS; h++) {
        const float* vh = val + h*16 + k;
        #pragma unroll
        for (int pp = 0; pp < 3; pp++) {
            int p = pp*2 + grp;
            float ox = sr[h*12 + p*2], oy = sr[h*12 + p*2 + 1];
            float aw = sr[96 + h*NPTS + p];
            float px = pxb + ox, py = pyb + oy;
            float fx = floorf(px), fy = floorf(py);
            int x0 = (int)fx, y0 = (int)fy;
            float wx = px - fx, wy = py - fy;
            bool xv0 = (x0 >= 0) && (x0 < WB_);
            bool xv1 = (x0 + 1 >= 0) && (x0 + 1 < WB_);
            float v = 0.f;
            if (y0 >= 0 && y0 < HB_) {
                const float* row0 = vh + (long long)y0*WB_*DIM;
                if (xv0) v += (1.f-wx)*(1.f-wy) * row0[(long long)x0*DIM];
                if (xv1) v += wx*(1.f-wy)       * row0[(long long)(x0+1)*DIM];
            }
            if (y0 + 1 >= 0 && y0 + 1 < HB_) {
                const float* row1 = vh + (long long)(y0+1)*WB_*DIM;
                if (xv0) v += (1.f-wx)*wy * row1[(long long)x0*DIM];
                if (xv1) v += wx*wy       * row1[(long long)(x0+1)*DIM];
            }
            acc[h] += aw * v;
        }
    }
    #pragma unroll
    for (int h = 0; h < NHEADS; h++) acc[h] += __shfl_xor_sync(0xffffffffu, acc[h], 16);
    if (lane < 16) {
        #pragma unroll
        for (int h = 0; h < NHEADS; h++) g_ms[(long long)m*DIM + h*16 + k] = acc[h];
    }
}

// ---------------- host driver -------------------------------------------------
extern "C" void kernel_launch(void* const* d_in, const int* in_sizes, int n_in,
                              void* d_out, int out_size) {
    const float* x_rv   = (const float*)d_in[0];
    const float* bev    = (const float*)d_in[1];
    const float* pq_w   = (const float*)d_in[2];
    const float* pq_b   = (const float*)d_in[3];
    const float* pv_w   = (const float*)d_in[4];
    const float* pv_b   = (const float*)d_in[5];
    const float* po_w   = (const float*)d_in[6];
    const float* po_b   = (const float*)d_in[7];
    const float* qs_w1  = (const float*)d_in[8];
    const float* qs_b1  = (const float*)d_in[9];
    const float* qs_w2  = (const float*)d_in[10];
    const float* qs_b2  = (const float*)d_in[11];
    const float* rh_w1  = (const float*)d_in[12];
    const float* rh_b1  = (const float*)d_in[13];
    const float* rh_g1  = (const float*)d_in[14];
    const float* rh_be1 = (const float*)d_in[15];
    const float* rh_w2  = (const float*)d_in[16];
    const float* rh_g2  = (const float*)d_in[17];
    const float* rh_be2 = (const float*)d_in[18];
    const float* rh_w3  = (const float*)d_in[19];
    const float* rh_b3  = (const float*)d_in[20];
    const float* so_w   = (const float*)d_in[21];
    const float* so_b   = (const float*)d_in[22];
    const float* aw_w   = (const float*)d_in[23];
    const float* aw_b   = (const float*)d_in[24];
    const float* vp_w   = (const float*)d_in[25];
    const float* vp_b   = (const float*)d_in[26];
    const float* op_w   = (const float*)d_in[27];
    const float* op_b   = (const float*)d_in[28];
    float* out = (float*)d_out;

    float *p_value, *p_Q0, *p_h1, *p_h2, *p_q1, *p_query, *p_sa, *p_ms, *p_sigfeat;
    float *p_Wv, *p_bv, *p_Wo, *p_bo, *p_Wsa, *p_bsa;
    cudaGetSymbolAddress((void**)&p_value,   g_value);
    cudaGetSymbolAddress((void**)&p_Q0,      g_Q0);
    cudaGetSymbolAddress((void**)&p_h1,      g_h1);
    cudaGetSymbolAddress((void**)&p_h2,      g_h2);
    cudaGetSymbolAddress((void**)&p_q1,      g_q1);
    cudaGetSymbolAddress((void**)&p_query,   g_query);
    cudaGetSymbolAddress((void**)&p_sa,      g_sa);
    cudaGetSymbolAddress((void**)&p_ms,      g_ms);
    cudaGetSymbolAddress((void**)&p_sigfeat, g_sigfeat);
    cudaGetSymbolAddress((void**)&p_Wv,      g_Wv);
    cudaGetSymbolAddress((void**)&p_bv,      g_bv);
    cudaGetSymbolAddress((void**)&p_Wo,      g_Wo);
    cudaGetSymbolAddress((void**)&p_bo,      g_bo);
    cudaGetSymbolAddress((void**)&p_Wsa,     g_Wsa);
    cudaGetSymbolAddress((void**)&p_bsa,     g_bsa);

    cudaFuncSetAttribute(conv3x3_kernel, cudaFuncAttributeMaxDynamicSharedMemorySize, CONV_SMEM);

    // 1. fuse weights
    prep_kernel<<<256, 128>>>(pv_w, pv_b, vp_w, vp_b, op_w, op_b, po_w, po_b,
                              so_w, so_b, aw_w, aw_b);

    // 2. value = bev^T @ Wv + bv  (M=40000/batch, K=256, A m-contiguous)
    gemm_kernel<<<dim3((NV_+BM-1)/BM, 1, 2), 256>>>(bev, 1LL, (long long)NV_, (long long)CB_*NV_,
                                          p_Wv, DIM, p_bv,
                                          p_value, (long long)NV_*DIM,
                                          NV_, CB_, DIM, 0, nullptr, 0);

    // 3. Q0 = x_rv @ pq_w + pq_b
    gemm_kernel<<<dim3(MQ/BM, 1, 1), 256>>>(x_rv, (long long)CRV_, 1LL, 0LL,
                                           pq_w, DIM, pq_b,
                                           p_Q0, 0LL, MQ, CRV_, DIM, 0, nullptr, 0);

    // 4. h1 = [x_rv | sin az | cos az] @ rh_w1 + rh_b1   (azimuth analytic)
    gemm_kernel<<<dim3(MQ/BM, 1, 1), 256>>>(x_rv, (long long)CRV_, 1LL, 0LL,
                                           rh_w1, DIM, rh_b1,
                                           p_h1, 0LL, MQ, CRV_, DIM, 1, nullptr, 0);

    // 5. GN1 stats (apply+GELU fused into conv staging)
    gn_partial<<<dim3(8, B_, 32), 256>>>(p_h1, 128, 16, NQPB, NQPB/32);
    gn_finalize<<<16, 32>>>(NQPB * 16);

    // 6. 3x3 circular conv 128->64 (with GN1+GELU on input staging)
    conv3x3_kernel<<<dim3(WRV_/CTJ, HRV_/CTI, B_), 256, CONV_SMEM>>>(p_h1, rh_w2, p_h2,
                                                                     rh_g1, rh_be1);

    // 7. GN2 stats, then fused GN2+GELU+rh3 head
    gn_partial<<<dim3(8, B_, 32), 256>>>(p_h2, 64, 8, NQPB, NQPB/32);
    gn_finalize<<<16, 32>>>(NQPB * 8);
    rh_final_kernel<<<MQ/128, 128>>>(p_h2, rh_g2, rh_be2, rh_w3, rh_b3);

    // 8. q1 = gelu([Q0 | sig_feat] @ qs_w1 + qs_b1)
    gemm_kernel<<<dim3(MQ/BM, 1, 1), 256>>>(p_Q0, (long long)DIM, 1LL, 0LL,
                                           qs_w1, DIM, qs_b1,
                                           p_q1, 0LL, MQ, DIM, DIM, 2, p_sigfeat, 1);

    // 9. query = q1 @ qs_w2 + qs_b2
    gemm_kernel<<<dim3(MQ/BM, 1, 1), 256>>>(p_q1, (long long)DIM, 1LL, 0LL,
                                           qs_w2, DIM, qs_b2,
                                           p_query, 0LL, MQ, DIM, DIM, 0, nullptr, 0);

    // 10. sampling offsets + attention logits: query @ [so_w | aw_w]
    gemm_kernel<<<dim3(MQ/BM, 2, 1), 256>>>(p_query, (long long)DIM, 1LL, 0LL,
                                           p_Wsa, 144, p_bsa,
                                           p_sa, 0LL, MQ, DIM, 144, 0, nullptr, 0);

    // 11. MSDA gather
    msda_kernel<<<MQ/8, 256>>>();

    // 12. y = ms @ (op_w@po_w) + fused bias  -> d_out
    gemm_kernel<<<dim3(MQ/BM, 1, 1), 256>>>(p_ms, (long long)DIM, 1LL, 0LL,
                                           p_Wo, DIM, p_bo,
                                           out, 0LL, MQ, DIM, DIM, 0, nullptr, 0);
}

// round 6
// speedup vs baseline: 1.3401x; 1.1197x over previous
#include <cuda_runtime.h>
#include <cuda_bf16.h>
#include <math.h>

#define B_   2
#define HRV_ 32
#define WRV_ 1024
#define NQPB 32768
#define MQ   65536
#define CRV_ 64
#define CB_  256
#define HB_  200
#define WB_  200
#define NV_  40000
#define DIM  128
#define NHEADS 8
#define NPTS 6

// ---------------- scratch (device globals; no allocation allowed) -------------
__device__ float g_Wv[CB_*DIM];
__device__ float g_bv[DIM];
__device__ float g_Wo[DIM*DIM];
__device__ float g_bo[DIM];
__device__ float g_Wsa[DIM*144];
__device__ float g_bsa[144];
__device__ float g_value[B_*NV_*DIM];     // [b, y*200+x, 128]
__device__ float g_Q0[MQ*DIM];
__device__ float g_h1[MQ*DIM];            // raw h1 (GN1+GELU applied in conv staging)
__device__ float g_h2[MQ*64];
__device__ float g_q1[MQ*DIM];
__device__ float g_query[MQ*DIM];
__device__ float g_sigfeat[MQ*2];
__device__ float g_refpx[MQ*2];           // rx*200-0.5, ry*200-0.5
__device__ float g_sa[MQ*144];            // [offs(96) | attw logits(48)]
__device__ float g_ms[MQ*DIM];
__device__ float g_gnstat[16*2];          // per (b,group): mean, rstd
__device__ float g_part[16*32*2];         // partial sums for GN stats

__device__ __forceinline__ float gelu_f(float x) {
    return 0.5f * x * (1.0f + erff(x * 0.70710678118654752440f));
}

// ---------------- weight fusion: Wv = pv_w@vp_w, Wo = op_w@po_w, Wsa=[so|aw] --
__global__ void prep_kernel(const float* __restrict__ pv_w, const float* __restrict__ pv_b,
                            const float* __restrict__ vp_w, const float* __restrict__ vp_b,
                            const float* __restrict__ op_w, const float* __restrict__ op_b,
                            const float* __restrict__ po_w, const float* __restrict__ po_b,
                            const float* __restrict__ so_w, const float* __restrict__ so_b,
                            const float* __restrict__ aw_w, const float* __restrict__ aw_b) {
    int r = blockIdx.x;      // 0..255
    int d = threadIdx.x;     // 0..127
    float acc = 0.f;
    for (int k = 0; k < 128; k++) acc += pv_w[r*128+k] * vp_w[k*128+d];
    g_Wv[r*128+d] = acc;
    if (r < 128) {
        float a2 = 0.f;
        for (int k = 0; k < 128; k++) a2 += op_w[r*128+k] * po_w[k*128+d];
        g_Wo[r*128+d] = a2;
        for (int n = d; n < 144; n += 128)
            g_Wsa[r*144+n] = (n < 96) ? so_w[r*96+n] : aw_w[r*48 + (n-96)];
    }
    if (r == 0) {
        float bv = 0.f, bo = 0.f;
        for (int k = 0; k < 128; k++) { bv += pv_b[k]*vp_w[k*128+d]; bo += op_b[k]*po_w[k*128+d]; }
        g_bv[d] = bv + vp_b[d];
        g_bo[d] = bo + po_b[d];
        for (int n = d; n < 144; n += 128)
            g_bsa[n] = (n < 96) ? so_b[n] : aw_b[n-96];
    }
}

// ---------------- tiled GEMM: C[M,N] = act(A@W + bias + ext) ------------------
// 128x128 block tile, 8x8 per-thread tile as 2x2 of 4x4 fragments (64 apart)
// -> conflict-free LDS.128 (lane i reads byte offset 16*i within each fragment).
// A element (m,k) at A[m*a_ms + k*a_ks]   (row-major: a_ks==1; bev: a_ms==1)
// ext_mode: 0 none, 1 azimuth(sin,cos at W rows K,K+1), 2 two floats from ext[m]
#define BM 128
#define BN 128
#define BK 16
#define APITCH (BM + 4)

__global__ __launch_bounds__(256, 2) void gemm_kernel(
    const float* __restrict__ A, long long a_ms, long long a_ks, long long a_bstride,
    const float* __restrict__ W, int ldw,
    const float* __restrict__ bias,
    float* __restrict__ C, long long c_bstride,
    int M, int K, int N,
    int ext_mode, const float* __restrict__ ext, int act_gelu)
{
    __shared__ float As[BK][APITCH];
    __shared__ float Ws[BK][BN];
    __shared__ float We[2][BN];
    const float* Ab = A + (long long)blockIdx.z * a_bstride;
    float* Cb = C + (long long)blockIdx.z * c_bstride;
    int m0 = blockIdx.x * BM, n0 = blockIdx.y * BN;
    int tid = threadIdx.x;
    int r4 = (tid >> 4) * 4;     // 0..60 (M fragment base; +64 for second)
    int c4 = (tid & 15) * 4;     // 0..60 (N fragment base; +64 for second)
    float acc[8][8] = {};
    bool akm = (a_ks == 1);

    for (int k0 = 0; k0 < K; k0 += BK) {
        if (akm) {
            // row-major A: 128 rows x 16 k, float4 per thread x2
            #pragma unroll
            for (int t = tid; t < BM*BK/4; t += 256) {
                int m = t >> 2;
                int kk = (t & 3) * 4;
                int gm = m0 + m;
                float4 v = make_float4(0.f, 0.f, 0.f, 0.f);
                if (gm < M) v = *(const float4*)&Ab[(long long)gm*a_ms + (k0 + kk)];
                As[kk  ][m] = v.x;
                As[kk+1][m] = v.y;
                As[kk+2][m] = v.z;
                As[kk+3][m] = v.w;
            }
        } else {
            // m-contiguous A (bev^T): direct coalesced
            #pragma unroll
            for (int t = tid; t < BK*BM; t += 256) {
                int k = t >> 7, m = t & 127;
                int gm = m0 + m;
                As[k][m] = (gm < M) ? Ab[(long long)(k0 + k)*a_ks + gm] : 0.f;
            }
        }
        #pragma unroll
        for (int t = tid; t < BK*BN/4; t += 256) {
            int k = t >> 5;
            int n = (t & 31) * 4;
            int gn = n0 + n;
            float4 v = make_float4(0.f, 0.f, 0.f, 0.f);
            if (gn < N) v = *(const float4*)&W[(long long)(k0 + k)*ldw + gn];
            *(float4*)&Ws[k][n] = v;
        }
        __syncthreads();
        #pragma unroll
        for (int k = 0; k < BK; k++) {
            float4 a0 = *(const float4*)&As[k][r4];
            float4 a1 = *(const float4*)&As[k][r4 + 64];
            float4 w0 = *(const float4*)&Ws[k][c4];
            float4 w1 = *(const float4*)&Ws[k][c4 + 64];
            float av[8] = {a0.x, a0.y, a0.z, a0.w, a1.x, a1.y, a1.z, a1.w};
            float wv[8] = {w0.x, w0.y, w0.z, w0.w, w1.x, w1.y, w1.z, w1.w};
            #pragma unroll
            for (int i = 0; i < 8; i++)
                #pragma unroll
                for (int j = 0; j < 8; j++)
                    acc[i][j] += av[i] * wv[j];
        }
        __syncthreads();
    }
    if (ext_mode) {
        for (int t = tid; t < 2*BN; t += 256) {
            int e = t >> 7, n = t & 127;
            int gn = n0 + n;
            We[e][n] = (gn < N) ? W[(long long)(K+e)*ldw + gn] : 0.f;
        }
        __syncthreads();
    }
    #pragma unroll
    for (int i = 0; i < 8; i++) {
        int lm = (i < 4) ? (r4 + i) : (r4 + 64 + i - 4);
        int gm = m0 + lm;
        if (gm >= M) continue;
        float e0 = 0.f, e1 = 0.f;
        if (ext_mode == 1) {
            int j = gm & (WRV_ - 1);
            float az = -3.14159265358979323846f + (float)j * (6.28318530717958647693f / (float)WRV_);
            e0 = sinf(az); e1 = cosf(az);
        } else if (ext_mode == 2) {
            e0 = ext[gm*2]; e1 = ext[gm*2+1];
        }
        #pragma unroll
        for (int f = 0; f < 2; f++) {
            int ln0 = c4 + f*64;
            int gn0 = n0 + ln0;
            if (gn0 >= N) continue;
            float o[4];
            #pragma unroll
            for (int j = 0; j < 4; j++) {
                float v = acc[i][f*4 + j];
                v += bias[gn0 + j];
                if (ext_mode) v += e0*We[0][ln0 + j] + e1*We[1][ln0 + j];
                if (act_gelu) v = gelu_f(v);
                o[j] = v;
            }
            *(float4*)&Cb[(long long)gm*N + gn0] = make_float4(o[0], o[1], o[2], o[3]);
        }
    }
}

// ---------------- group-norm stats (two stage) --------------------------------
__global__ void gn_partial(const float* __restrict__ x, int C, int cg,
                           int rowsPerB, int rowsPerChunk) {
    int g = blockIdx.x, b = blockIdx.y, ch = blockIdx.z;
    int G = gridDim.x;
    const float* xb = x + ((long long)b*rowsPerB + (long long)ch*rowsPerChunk)*C;
    int total = rowsPerChunk * cg;
    float s = 0.f, s2 = 0.f;
    for (int t = threadIdx.x; t < total; t += blockDim.x) {
        int r = t / cg, c = g*cg + (t - (t/cg)*cg);
        float v = xb[(long long)r*C + c];
        s += v; s2 += v*v;
    }
    __shared__ float sh[256], sh2[256];
    sh[threadIdx.x] = s; sh2[threadIdx.x] = s2;
    __syncthreads();
    for (int off = 128; off > 0; off >>= 1) {
        if (threadIdx.x < off) { sh[threadIdx.x] += sh[threadIdx.x+off]; sh2[threadIdx.x] += sh2[threadIdx.x+off]; }
        __syncthreads();
    }
    if (threadIdx.x == 0) {
        int idx = ((b*G + g)*32 + ch)*2;
        g_part[idx] = sh[0]; g_part[idx+1] = sh2[0];
    }
}

__global__ void gn_finalize(int total) {   // grid = B*G blocks of 32 threads
    int bg = blockIdx.x, lane = threadIdx.x;
    float s = g_part[(bg*32+lane)*2], s2 = g_part[(bg*32+lane)*2+1];
    for (int off = 16; off; off >>= 1) {
        s  += __shfl_down_sync(0xffffffffu, s,  off);
        s2 += __shfl_down_sync(0xffffffffu, s2, off);
    }
    if (lane == 0) {
        float mean = s / (float)total;
        float var = s2 / (float)total - mean*mean;
        g_gnstat[bg*2]   = mean;
        g_gnstat[bg*2+1] = rsqrtf(var + 1e-5f);
    }
}

// ---------------- 3x3 circular conv, 128 -> 64 ch, GN1+GELU fused in staging --
#define CTI 4
#define CTJ 32
#define CCT 32
#define SPITCH 33
#define CONV_SIN  (6*34*SPITCH)        // 6732 floats
#define CONV_SW   (9*CCT*64)           // 18432 floats
#define CONV_SMEM ((CONV_SIN + CONV_SW)*4)

__global__ __launch_bounds__(256) void conv3x3_kernel(
    const float* __restrict__ hin, const float* __restrict__ w2, float* __restrict__ hout,
    const float* __restrict__ g1, const float* __restrict__ be1)
{
    extern __shared__ float smem[];
    float* sIn = smem;
    float* sW  = smem + CONV_SIN;
    int bj = blockIdx.x, bi = blockIdx.y, b = blockIdx.z;
    int tid = threadIdx.x;
    int lane = tid & 31, wid = tid >> 5;
    int oc_base = wid * 8;
    float acc[4][8];
    #pragma unroll
    for (int u = 0; u < 4; u++)
        #pragma unroll
        for (int o = 0; o < 8; o++) acc[u][o] = 0.f;

    for (int ct = 0; ct < 128; ct += CCT) {
        __syncthreads();
        // stage input patch [6 rows][34 cols][32 ch] with circular wrap; apply GN1+GELU
        for (int t = tid; t < 6*34*CCT; t += 256) {
            int li = t / (34*CCT);
            int rem = t - li*(34*CCT);
            int lj = rem / CCT;
            int cc = rem - lj*CCT;
            int gi = (bi*CTI + li - 1 + HRV_) & (HRV_ - 1);
            int gj = (bj*CTJ + lj - 1 + WRV_) & (WRV_ - 1);
            int c  = ct + cc;
            float v = hin[(((long long)b*HRV_ + gi)*WRV_ + gj)*128 + c];
            int g = c >> 4;
            float mean = g_gnstat[(b*8+g)*2], rstd = g_gnstat[(b*8+g)*2+1];
            sIn[(li*34 + lj)*SPITCH + cc] = gelu_f((v - mean)*rstd*g1[c] + be1[c]);
        }
        // stage weight chunk [9][32 ic][64 oc]
        for (int t = tid; t < 9*CCT*64; t += 256) {
            int rc = t / (CCT*64);
            int rem = t - rc*(CCT*64);
            int ic = rem >> 6;
            int oc = rem & 63;
            sW[t] = w2[((long long)rc*128 + ct + ic)*64 + oc];
        }
        __syncthreads();
        #pragma unroll
        for (int rc = 0; rc < 9; rc++) {
            int r = rc / 3, c = rc - r*3;
            const float* wr = sW + rc*CCT*64 + oc_base;
            const float* ir = sIn + (r*34 + lane + c)*SPITCH;
            #pragma unroll 4
            for (int cc = 0; cc < CCT; cc++) {
                float4 wa = *(const float4*)(wr + cc*64);
                float4 wb = *(const float4*)(wr + cc*64 + 4);
                float iv[4];
                #pragma unroll
                for (int u = 0; u < 4; u++) iv[u] = ir[u*(34*SPITCH) + cc];
                #pragma unroll
                for (int u = 0; u < 4; u++) {
                    acc[u][0] += iv[u]*wa.x; acc[u][1] += iv[u]*wa.y;
                    acc[u][2] += iv[u]*wa.z; acc[u][3] += iv[u]*wa.w;
                    acc[u][4] += iv[u]*wb.x; acc[u][5] += iv[u]*wb.y;
                    acc[u][6] += iv[u]*wb.z; acc[u][7] += iv[u]*wb.w;
                }
            }
        }
    }
    #pragma unroll
    for (int u = 0; u < 4; u++) {
        long long o = (((long long)b*HRV_ + bi*CTI + u)*WRV_ + bj*CTJ + lane)*64 + oc_base;
        *(float4*)(hout + o)     = make_float4(acc[u][0], acc[u][1], acc[u][2], acc[u][3]);
        *(float4*)(hout + o + 4) = make_float4(acc[u][4], acc[u][5], acc[u][6], acc[u][7]);
    }
}

// ---------------- GN2 + GELU + rh3 head + reference points --------------------
__global__ __launch_bounds__(128) void rh_final_kernel(
    const float* __restrict__ h2, const float* __restrict__ g2, const float* __restrict__ be2,
    const float* __restrict__ w3, const float* __restrict__ b3)
{
    __shared__ float sh[128*65];
    int m0 = blockIdx.x * 128;
    for (int t = threadIdx.x; t < 128*64; t += 128) {
        int r = t >> 6, c = t & 63;
        sh[r*65 + c] = h2[(long long)(m0 + r)*64 + c];
    }
    __syncthreads();
    int m = m0 + threadIdx.x;
    int b = m >> 15;   // /32768
    const float* row = &sh[threadIdx.x*65];
    float mu = 0.f, ls = 0.f;
    #pragma unroll
    for (int c = 0; c < 64; c++) {
        int g = c >> 3;
        float mean = g_gnstat[(b*8+g)*2], rstd = g_gnstat[(b*8+g)*2+1];
        float v = (row[c] - mean) * rstd * g2[c] + be2[c];
        v = gelu_f(v);
        mu += v * w3[c*2];
        ls += v * w3[c*2+1];
    }
    mu += b3[0]; ls += b3[1];
    mu = fminf(fmaxf(mu, 0.f), 55.f);
    ls = fminf(fmaxf(ls, -5.f), 3.f);
    float sig = expf(ls);
    g_sigfeat[m*2]   = ls;
    g_sigfeat[m*2+1] = 1.f / (sig + 1e-6f);
    int j = m & (WRV_ - 1);
    float az = -3.14159265358979323846f + (float)j * (6.28318530717958647693f / (float)WRV_);
    float xmu = mu * cosf(az), ymu = mu * sinf(az);
    float rx = fminf(fmaxf((xmu + 50.f) * 0.01f, 0.f), 1.f);
    float ry = fminf(fmaxf((ymu + 50.f) * 0.01f, 0.f), 1.f);
    g_refpx[m*2]   = rx * (float)WB_ - 0.5f;
    g_refpx[m*2+1] = ry * (float)HB_ - 0.5f;
}

// ---------------- MSDA: softmax + bilinear gather + weighted sum --------------
__global__ __launch_bounds__(256) void msda_kernel() {
    __shared__ float s[8][160];
    int wid = threadIdx.x >> 5, lane = threadIdx.x & 31;
    int m = blockIdx.x * 8 + wid;
    int b = m >> 15;
    float* sr = s[wid];
    for (int t = lane; t < 144; t += 32) sr[t] = g_sa[(long long)m*144 + t];
    __syncwarp();
    if (lane < NHEADS) {
        float mx = -1e30f;
        #pragma unroll
        for (int p = 0; p < NPTS; p++) mx = fmaxf(mx, sr[96 + lane*NPTS + p]);
        float e[NPTS], sum = 0.f;
        #pragma unroll
        for (int p = 0; p < NPTS; p++) { e[p] = expf(sr[96 + lane*NPTS + p] - mx); sum += e[p]; }
        float inv = 1.f / sum;
        #pragma unroll
        for (int p = 0; p < NPTS; p++) sr[96 + lane*NPTS + p] = e[p] * inv;
    }
    __syncwarp();
    float pxb = g_refpx[m*2], pyb = g_refpx[m*2+1];
    int grp = lane >> 4, k = lane & 15;
    const float* val = g_value + (long long)b*NV_*DIM;
    float acc[NHEADS];
    #pragma unroll
    for (int h = 0; h < NHEADS; h++) acc[h] = 0.f;
    #pragma unroll
    for (int h = 0; h < NHEADS; h++) {
        const float* vh = val + h*16 + k;
        #pragma unroll
        for (int pp = 0; pp < 3; pp++) {
            int p = pp*2 + grp;
            float ox = sr[h*12 + p*2], oy = sr[h*12 + p*2 + 1];
            float aw = sr[96 + h*NPTS + p];
            float px = pxb + ox, py = pyb + oy;
            float fx = floorf(px), fy = floorf(py);
            int x0 = (int)fx, y0 = (int)fy;
            float wx = px - fx, wy = py - fy;
            bool xv0 = (x0 >= 0) && (x0 < WB_);
            bool xv1 = (x0 + 1 >= 0) && (x0 + 1 < WB_);
            float v = 0.f;
            if (y0 >= 0 && y0 < HB_) {
                const float* row0 = vh + (long long)y0*WB_*DIM;
                if (xv0) v += (1.f-wx)*(1.f-wy) * row0[(long long)x0*DIM];
                if (xv1) v += wx*(1.f-wy)       * row0[(long long)(x0+1)*DIM];
            }
            if (y0 + 1 >= 0 && y0 + 1 < HB_) {
                const float* row1 = vh + (long long)(y0+1)*WB_*DIM;
                if (xv0) v += (1.f-wx)*wy * row1[(long long)x0*DIM];
                if (xv1) v += wx*wy       * row1[(long long)(x0+1)*DIM];
            }
            acc[h] += aw * v;
        }
    }
    #pragma unroll
    for (int h = 0; h < NHEADS; h++) acc[h] += __shfl_xor_sync(0xffffffffu, acc[h], 16);
    if (lane < 16) {
        #pragma unroll
        for (int h = 0; h < NHEADS; h++) g_ms[(long long)m*DIM + h*16 + k] = acc[h];
    }
}

// ---------------- host driver -------------------------------------------------
extern "C" void kernel_launch(void* const* d_in, const int* in_sizes, int n_in,
                              void* d_out, int out_size) {
    const float* x_rv   = (const float*)d_in[0];
    const float* bev    = (const float*)d_in[1];
    const float* pq_w   = (const float*)d_in[2];
    const float* pq_b   = (const float*)d_in[3];
    const float* pv_w   = (const float*)d_in[4];
    const float* pv_b   = (const float*)d_in[5];
    const float* po_w   = (const float*)d_in[6];
    const float* po_b   = (const float*)d_in[7];
    const float* qs_w1  = (const float*)d_in[8];
    const float* qs_b1  = (const float*)d_in[9];
    const float* qs_w2  = (const float*)d_in[10];
    const float* qs_b2  = (const float*)d_in[11];
    const float* rh_w1  = (const float*)d_in[12];
    const float* rh_b1  = (const float*)d_in[13];
    const float* rh_g1  = (const float*)d_in[14];
    const float* rh_be1 = (const float*)d_in[15];
    const float* rh_w2  = (const float*)d_in[16];
    const float* rh_g2  = (const float*)d_in[17];
    const float* rh_be2 = (const float*)d_in[18];
    const float* rh_w3  = (const float*)d_in[19];
    const float* rh_b3  = (const float*)d_in[20];
    const float* so_w   = (const float*)d_in[21];
    const float* so_b   = (const float*)d_in[22];
    const float* aw_w   = (const float*)d_in[23];
    const float* aw_b   = (const float*)d_in[24];
    const float* vp_w   = (const float*)d_in[25];
    const float* vp_b   = (const float*)d_in[26];
    const float* op_w   = (const float*)d_in[27];
    const float* op_b   = (const float*)d_in[28];
    float* out = (float*)d_out;

    float *p_value, *p_Q0, *p_h1, *p_h2, *p_q1, *p_query, *p_sa, *p_ms, *p_sigfeat;
    float *p_Wv, *p_bv, *p_Wo, *p_bo, *p_Wsa, *p_bsa;
    cudaGetSymbolAddress((void**)&p_value,   g_value);
    cudaGetSymbolAddress((void**)&p_Q0,      g_Q0);
    cudaGetSymbolAddress((void**)&p_h1,      g_h1);
    cudaGetSymbolAddress((void**)&p_h2,      g_h2);
    cudaGetSymbolAddress((void**)&p_q1,      g_q1);
    cudaGetSymbolAddress((void**)&p_query,   g_query);
    cudaGetSymbolAddress((void**)&p_sa,      g_sa);
    cudaGetSymbolAddress((void**)&p_ms,      g_ms);
    cudaGetSymbolAddress((void**)&p_sigfeat, g_sigfeat);
    cudaGetSymbolAddress((void**)&p_Wv,      g_Wv);
    cudaGetSymbolAddress((void**)&p_bv,      g_bv);
    cudaGetSymbolAddress((void**)&p_Wo,      g_Wo);
    cudaGetSymbolAddress((void**)&p_bo,      g_bo);
    cudaGetSymbolAddress((void**)&p_Wsa,     g_Wsa);
    cudaGetSymbolAddress((void**)&p_bsa,     g_bsa);

    cudaFuncSetAttribute(conv3x3_kernel, cudaFuncAttributeMaxDynamicSharedMemorySize, CONV_SMEM);

    // 1. fuse weights
    prep_kernel<<<256, 128>>>(pv_w, pv_b, vp_w, vp_b, op_w, op_b, po_w, po_b,
                              so_w, so_b, aw_w, aw_b);

    // 2. value = bev^T @ Wv + bv  (M=40000/batch, K=256, A m-contiguous)
    gemm_kernel<<<dim3((NV_+BM-1)/BM, 1, 2), 256>>>(bev, 1LL, (long long)NV_, (long long)CB_*NV_,
                                          p_Wv, DIM, p_bv,
                                          p_value, (long long)NV_*DIM,
                                          NV_, CB_, DIM, 0, nullptr, 0);

    // 3. Q0 = x_rv @ pq_w + pq_b
    gemm_kernel<<<dim3(MQ/BM, 1, 1), 256>>>(x_rv, (long long)CRV_, 1LL, 0LL,
                                           pq_w, DIM, pq_b,
                                           p_Q0, 0LL, MQ, CRV_, DIM, 0, nullptr, 0);

    // 4. h1 = [x_rv | sin az | cos az] @ rh_w1 + rh_b1   (azimuth analytic)
    gemm_kernel<<<dim3(MQ/BM, 1, 1), 256>>>(x_rv, (long long)CRV_, 1LL, 0LL,
                                           rh_w1, DIM, rh_b1,
                                           p_h1, 0LL, MQ, CRV_, DIM, 1, nullptr, 0);

    // 5. GN1 stats (apply+GELU fused into conv staging)
    gn_partial<<<dim3(8, B_, 32), 256>>>(p_h1, 128, 16, NQPB, NQPB/32);
    gn_finalize<<<16, 32>>>(NQPB * 16);

    // 6. 3x3 circular conv 128->64 (with GN1+GELU on input staging)
    conv3x3_kernel<<<dim3(WRV_/CTJ, HRV_/CTI, B_), 256, CONV_SMEM>>>(p_h1, rh_w2, p_h2,
                                                                     rh_g1, rh_be1);

    // 7. GN2 stats, then fused GN2+GELU+rh3 head
    gn_partial<<<dim3(8, B_, 32), 256>>>(p_h2, 64, 8, NQPB, NQPB/32);
    gn_finalize<<<16, 32>>>(NQPB * 8);
    rh_final_kernel<<<MQ/128, 128>>>(p_h2, rh_g2, rh_be2, rh_w3, rh_b3);

    // 8. q1 = gelu([Q0 | sig_feat] @ qs_w1 + qs_b1)
    gemm_kernel<<<dim3(MQ/BM, 1, 1), 256>>>(p_Q0, (long long)DIM, 1LL, 0LL,
                                           qs_w1, DIM, qs_b1,
                                           p_q1, 0LL, MQ, DIM, DIM, 2, p_sigfeat, 1);

    // 9. query = q1 @ qs_w2 + qs_b2
    gemm_kernel<<<dim3(MQ/BM, 1, 1), 256>>>(p_q1, (long long)DIM, 1LL, 0LL,
                                           qs_w2, DIM, qs_b2,
                                           p_query, 0LL, MQ, DIM, DIM, 0, nullptr, 0);

    // 10. sampling offsets + attention logits: query @ [so_w | aw_w]
    gemm_kernel<<<dim3(MQ/BM, 2, 1), 256>>>(p_query, (long long)DIM, 1LL, 0LL,
                                           p_Wsa, 144, p_bsa,
                                           p_sa, 0LL, MQ, DIM, 144, 0, nullptr, 0);

    // 11. MSDA gather
    msda_kernel<<<MQ/8, 256>>>();

    // 12. y = ms @ (op_w@po_w) + fused bias  -> d_out
    gemm_kernel<<<dim3(MQ/BM, 1, 1), 256>>>(p_ms, (long long)DIM, 1LL, 0LL,
                                           p_Wo, DIM, p_bo,
                                           out, 0LL, MQ, DIM, DIM, 0, nullptr, 0);
}